// round 1
// baseline (speedup 1.0000x reference)
#include <cuda_runtime.h>

// TinyFormerEncoder: B=65536, S=16, D=32, FFN=64, fp32.
// Fully fused: one warp processes 2 batches (lane = g*16 + token).
// Weights in shared (broadcast LDS.128), x row in registers, K/V staged in a
// reused per-warp shared buffer. Inner loops use packed fma.rn.f32x2 (FFMA2)
// to reach 128 lane-FMA/cyc/SM instead of 64 with plain FFMA.

#define DDIM 32
#define SEQ  16
#define FFND 64
#define NBAT 65536
#define NWARP 4
#define CTA   128
#define NBLK  444   // 148 SMs * 3 CTAs

typedef unsigned long long u64;

__device__ __forceinline__ u64 pk2(float lo, float hi) {
    u64 r; asm("mov.b64 %0,{%1,%2};" : "=l"(r) : "f"(lo), "f"(hi)); return r;
}
__device__ __forceinline__ void upk2(u64 p, float &lo, float &hi) {
    asm("mov.b64 {%0,%1},%2;" : "=f"(lo), "=f"(hi) : "l"(p));
}
__device__ __forceinline__ void fma2(u64 &d, u64 a, u64 b) {
    asm("fma.rn.f32x2 %0,%1,%2,%0;" : "+l"(d) : "l"(a), "l"(b));
}
__device__ __forceinline__ u64 add2(u64 a, u64 b) {
    u64 r; asm("add.rn.f32x2 %0,%1,%2;" : "=l"(r) : "l"(a), "l"(b)); return r;
}

// acc[p] packs output dims (2p, 2p+1). 32-in -> 32-out GEMM from shared W [32][32].
__device__ __forceinline__ void gemm_32to32(const float* __restrict__ Wsh,
                                            const float* xin, u64* acc) {
#pragma unroll
    for (int k = 0; k < 32; k++) {
        u64 xd = pk2(xin[k], xin[k]);
        const ulonglong2* w = reinterpret_cast<const ulonglong2*>(Wsh + k * 32);
#pragma unroll
        for (int j = 0; j < 8; j++) {
            ulonglong2 ww = w[j];
            fma2(acc[2 * j],     xd, ww.x);
            fma2(acc[2 * j + 1], xd, ww.y);
        }
    }
}

__device__ __forceinline__ void bias16(u64* acc, const float* __restrict__ bsh) {
    const ulonglong2* bb = reinterpret_cast<const ulonglong2*>(bsh);
#pragma unroll
    for (int j = 0; j < 8; j++) {
        ulonglong2 b = bb[j];
        acc[2 * j]     = add2(acc[2 * j],     b.x);
        acc[2 * j + 1] = add2(acc[2 * j + 1], b.y);
    }
}

__device__ __forceinline__ void store_row(float* row, const u64* acc) {
    ulonglong2* rp = reinterpret_cast<ulonglong2*>(row);
#pragma unroll
    for (int j = 0; j < 8; j++) {
        ulonglong2 tt; tt.x = acc[2 * j]; tt.y = acc[2 * j + 1];
        rp[j] = tt;
    }
}

// Shared layout (floats): Wq 0, Wk 1024, Wv 2048, Wo 3072, W1 4096(2048), W2 6144(2048),
// biases 8192..8415 (bq,bk,bv,bo @ +0/32/64/96; b1 @ +128(64); b2 @ +192), pad to 8448,
// then per-warp KV buffers: warp stride 1168 floats, group stride 584, row stride 36.
#define SMF_B   8192
#define SMF_KV  8448
#define KV_WSTR 1168
#define KV_GSTR 584
#define KV_RSTR 36
#define SMEM_FLOATS (SMF_KV + NWARP * KV_WSTR)   // 13120 floats = 52480 B

extern "C" __global__ void __launch_bounds__(CTA, 3)
tfenc_kernel(const float* __restrict__ x,
             const float* __restrict__ Wq, const float* __restrict__ bq,
             const float* __restrict__ Wk, const float* __restrict__ bk,
             const float* __restrict__ Wv, const float* __restrict__ bv,
             const float* __restrict__ Wo, const float* __restrict__ bo,
             const float* __restrict__ W1, const float* __restrict__ b1,
             const float* __restrict__ W2, const float* __restrict__ b2,
             float* __restrict__ out)
{
    extern __shared__ float sm[];
    float* sWq = sm;
    float* sWk = sm + 1024;
    float* sWv = sm + 2048;
    float* sWo = sm + 3072;
    float* sW1 = sm + 4096;
    float* sW2 = sm + 6144;
    float* sB  = sm + SMF_B;
    float* sKV = sm + SMF_KV;

    const int tid = threadIdx.x;
    for (int i = tid; i < 1024; i += CTA) {
        sWq[i] = Wq[i]; sWk[i] = Wk[i]; sWv[i] = Wv[i]; sWo[i] = Wo[i];
    }
    for (int i = tid; i < 2048; i += CTA) { sW1[i] = W1[i]; sW2[i] = W2[i]; }
    if (tid < 32) {
        sB[tid] = bq[tid]; sB[32 + tid] = bk[tid]; sB[64 + tid] = bv[tid];
        sB[96 + tid] = bo[tid]; sB[192 + tid] = b2[tid];
    }
    if (tid >= 32 && tid < 96) sB[96 + tid] = b1[tid - 32];   // -> sB[128..191]
    __syncthreads();

    const int warp = tid >> 5, lane = tid & 31;
    const int g = lane >> 4;      // which batch of the pair
    const int t = lane & 15;      // token owned by this lane
    float* kv = sKV + warp * KV_WSTR + g * KV_GSTR;

    const int npairs  = NBAT / 2;
    const int pstride = gridDim.x * NWARP;
    for (int pair = blockIdx.x * NWARP + warp; pair < npairs; pair += pstride) {
        const int b = pair * 2 + g;
        const float* xrow = x + ((long)b * SEQ + t) * DDIM;

        float xv[32];
#pragma unroll
        for (int j = 0; j < 8; j++) {
            float4 f = reinterpret_cast<const float4*>(xrow)[j];
            xv[4 * j] = f.x; xv[4 * j + 1] = f.y; xv[4 * j + 2] = f.z; xv[4 * j + 3] = f.w;
        }

        // ---- Q (kept packed as pairs for the scores stage) ----
        u64 q2[16];
#pragma unroll
        for (int p = 0; p < 16; p++) q2[p] = 0ULL;
        gemm_32to32(sWq, xv, q2);
        bias16(q2, sB + 0);

        // ---- K -> shared ----
        {
            u64 a[16];
#pragma unroll
            for (int p = 0; p < 16; p++) a[p] = 0ULL;
            gemm_32to32(sWk, xv, a);
            bias16(a, sB + 32);
            store_row(kv + t * KV_RSTR, a);
        }
        __syncwarp();

        // ---- scores: sc[t'] = q . k_t' * 1/sqrt(D) ----
        float sc[16];
#pragma unroll
        for (int tt = 0; tt < 16; tt++) {
            const ulonglong2* kr = reinterpret_cast<const ulonglong2*>(kv + tt * KV_RSTR);
            u64 a0 = 0ULL, a1 = 0ULL;
#pragma unroll
            for (int j = 0; j < 8; j++) {
                ulonglong2 kk = kr[j];
                fma2(a0, q2[2 * j],     kk.x);
                fma2(a1, q2[2 * j + 1], kk.y);
            }
            float l0, h0, l1, h1;
            upk2(a0, l0, h0); upk2(a1, l1, h1);
            sc[tt] = (l0 + h0 + l1 + h1) * 0.17677669529663689f;
        }
        __syncwarp();   // all lanes done reading K before V overwrites buffer

        // ---- softmax over 16 scores ----
        float m = sc[0];
#pragma unroll
        for (int i = 1; i < 16; i++) m = fmaxf(m, sc[i]);
        float sum = 0.f;
#pragma unroll
        for (int i = 0; i < 16; i++) { float e = __expf(sc[i] - m); sc[i] = e; sum += e; }
        const float inv = 1.0f / sum;

        // ---- V -> shared (reuse buffer) ----
        {
            u64 a[16];
#pragma unroll
            for (int p = 0; p < 16; p++) a[p] = 0ULL;
            gemm_32to32(sWv, xv, a);
            bias16(a, sB + 64);
            store_row(kv + t * KV_RSTR, a);
        }
        __syncwarp();

        // ---- context = sum_t attn_t * v_t ----
        u64 c2[16];
#pragma unroll
        for (int p = 0; p < 16; p++) c2[p] = 0ULL;
#pragma unroll
        for (int tt = 0; tt < 16; tt++) {
            const float aw = sc[tt] * inv;
            const u64 ad = pk2(aw, aw);
            const ulonglong2* vr = reinterpret_cast<const ulonglong2*>(kv + tt * KV_RSTR);
#pragma unroll
            for (int j = 0; j < 8; j++) {
                ulonglong2 vv = vr[j];
                fma2(c2[2 * j],     ad, vv.x);
                fma2(c2[2 * j + 1], ad, vv.y);
            }
        }
        __syncwarp();   // done reading V before next iteration's K store

        // ---- Wo + residual 1 ----
        float c[32];
#pragma unroll
        for (int p = 0; p < 16; p++) upk2(c2[p], c[2 * p], c[2 * p + 1]);
        u64 y2[16];
#pragma unroll
        for (int p = 0; p < 16; p++) y2[p] = 0ULL;
        gemm_32to32(sWo, c, y2);
        float y[32];
#pragma unroll
        for (int p = 0; p < 16; p++) {
            float lo, hi; upk2(y2[p], lo, hi);
            y[2 * p]     = xv[2 * p]     + lo + sB[96 + 2 * p];
            y[2 * p + 1] = xv[2 * p + 1] + hi + sB[96 + 2 * p + 1];
        }

        // ---- FFN1: h = relu(y @ W1 + b1), 64 outs ----
        u64 h2[32];
#pragma unroll
        for (int p = 0; p < 32; p++) h2[p] = 0ULL;
#pragma unroll
        for (int k = 0; k < 32; k++) {
            u64 yd = pk2(y[k], y[k]);
            const ulonglong2* w = reinterpret_cast<const ulonglong2*>(sW1 + k * 64);
#pragma unroll
            for (int j = 0; j < 16; j++) {
                ulonglong2 ww = w[j];
                fma2(h2[2 * j],     yd, ww.x);
                fma2(h2[2 * j + 1], yd, ww.y);
            }
        }
        float h[64];
#pragma unroll
        for (int p = 0; p < 32; p++) {
            float lo, hi; upk2(h2[p], lo, hi);
            h[2 * p]     = fmaxf(lo + sB[128 + 2 * p],     0.f);
            h[2 * p + 1] = fmaxf(hi + sB[128 + 2 * p + 1], 0.f);
        }

        // ---- FFN2 + residual 2 + store ----
        u64 z2[16];
#pragma unroll
        for (int p = 0; p < 16; p++) z2[p] = 0ULL;
#pragma unroll
        for (int f = 0; f < 64; f++) {
            u64 hd = pk2(h[f], h[f]);
            const ulonglong2* w = reinterpret_cast<const ulonglong2*>(sW2 + f * 32);
#pragma unroll
            for (int j = 0; j < 8; j++) {
                ulonglong2 ww = w[j];
                fma2(z2[2 * j],     hd, ww.x);
                fma2(z2[2 * j + 1], hd, ww.y);
            }
        }
        float* orow = out + ((long)b * SEQ + t) * DDIM;
#pragma unroll
        for (int j = 0; j < 8; j++) {
            float l0, h0v, l1, h1v;
            upk2(z2[2 * j], l0, h0v); upk2(z2[2 * j + 1], l1, h1v);
            float4 f;
            f.x = y[4 * j]     + l0  + sB[192 + 4 * j];
            f.y = y[4 * j + 1] + h0v + sB[192 + 4 * j + 1];
            f.z = y[4 * j + 2] + l1  + sB[192 + 4 * j + 2];
            f.w = y[4 * j + 3] + h1v + sB[192 + 4 * j + 3];
            reinterpret_cast<float4*>(orow)[j] = f;
        }
    }
}

extern "C" void kernel_launch(void* const* d_in, const int* in_sizes, int n_in,
                              void* d_out, int out_size) {
    (void)in_sizes; (void)n_in; (void)out_size;
    const float* x  = (const float*)d_in[0];
    const float* Wq = (const float*)d_in[1];
    const float* bq = (const float*)d_in[2];
    const float* Wk = (const float*)d_in[3];
    const float* bk = (const float*)d_in[4];
    const float* Wv = (const float*)d_in[5];
    const float* bv = (const float*)d_in[6];
    const float* Wo = (const float*)d_in[7];
    const float* bo = (const float*)d_in[8];
    const float* W1 = (const float*)d_in[9];
    const float* b1 = (const float*)d_in[10];
    const float* W2 = (const float*)d_in[11];
    const float* b2 = (const float*)d_in[12];
    float* out = (float*)d_out;

    const int smem_bytes = SMEM_FLOATS * 4;   // 52480
    cudaFuncSetAttribute(tfenc_kernel, cudaFuncAttributeMaxDynamicSharedMemorySize, smem_bytes);
    tfenc_kernel<<<NBLK, CTA, smem_bytes>>>(x, Wq, bq, Wk, bk, Wv, bv, Wo, bo,
                                            W1, b1, W2, b2, out);
}

// round 2
// speedup vs baseline: 1.1696x; 1.1696x over previous
#include <cuda_runtime.h>

// TinyFormerEncoder: B=65536, S=16, D=32, FFN=64, fp32.
// Round 2: dual-token per lane. Warp = 4 batches; lane (g,t) processes token t
// of batches (quad*4+g) and (quad*4+2+g). Every weight LDS.128 (broadcast)
// now feeds 4 FFMA2 (2 tokens x f32x2), halving weight LDS traffic, which
// Round-1 ncu showed was the binder (L1 pipe 80%, fma 36%).

#define DDIM 32
#define SEQ  16
#define FFND 64
#define NBAT 65536
#define NWARP 4
#define CTA   128
#define NBLK  296   // 148 SMs * 2 CTAs

typedef unsigned long long u64;

__device__ __forceinline__ u64 pk2(float lo, float hi) {
    u64 r; asm("mov.b64 %0,{%1,%2};" : "=l"(r) : "f"(lo), "f"(hi)); return r;
}
__device__ __forceinline__ void upk2(u64 p, float &lo, float &hi) {
    asm("mov.b64 {%0,%1},%2;" : "=f"(lo), "=f"(hi) : "l"(p));
}
__device__ __forceinline__ void fma2(u64 &d, u64 a, u64 b) {
    asm("fma.rn.f32x2 %0,%1,%2,%0;" : "+l"(d) : "l"(a), "l"(b));
}
__device__ __forceinline__ u64 add2(u64 a, u64 b) {
    u64 r; asm("add.rn.f32x2 %0,%1,%2;" : "=l"(r) : "l"(a), "l"(b)); return r;
}

// Dual-token 32->32 GEMM from shared W[32][32]. One weight row load feeds both.
__device__ __forceinline__ void gemm_32to32_dual(const float* __restrict__ Wsh,
                                                 const float* xa, const float* xb,
                                                 u64* accA, u64* accB) {
#pragma unroll
    for (int k = 0; k < 32; k++) {
        u64 xda = pk2(xa[k], xa[k]);
        u64 xdb = pk2(xb[k], xb[k]);
        const ulonglong2* w = reinterpret_cast<const ulonglong2*>(Wsh + k * 32);
#pragma unroll
        for (int j = 0; j < 8; j++) {
            ulonglong2 ww = w[j];
            fma2(accA[2 * j],     xda, ww.x);
            fma2(accA[2 * j + 1], xda, ww.y);
            fma2(accB[2 * j],     xdb, ww.x);
            fma2(accB[2 * j + 1], xdb, ww.y);
        }
    }
}

__device__ __forceinline__ void bias16(u64* acc, const float* __restrict__ bsh) {
    const ulonglong2* bb = reinterpret_cast<const ulonglong2*>(bsh);
#pragma unroll
    for (int j = 0; j < 8; j++) {
        ulonglong2 b = bb[j];
        acc[2 * j]     = add2(acc[2 * j],     b.x);
        acc[2 * j + 1] = add2(acc[2 * j + 1], b.y);
    }
}

__device__ __forceinline__ void store_row(float* row, const u64* acc) {
    ulonglong2* rp = reinterpret_cast<ulonglong2*>(row);
#pragma unroll
    for (int j = 0; j < 8; j++) {
        ulonglong2 tt; tt.x = acc[2 * j]; tt.y = acc[2 * j + 1];
        rp[j] = tt;
    }
}

// Shared layout (floats): Wq 0, Wk 1024, Wv 2048, Wo 3072, W1 4096(2048), W2 6144(2048),
// biases 8192..8415 (bq,bk,bv,bo @ +0/32/64/96; b1 @ +128(64); b2 @ +192), pad to 8448,
// then per-warp KV buffers: 4 groups/warp, group stride 584, row stride 36.
#define SMF_B   8192
#define SMF_KV  8448
#define KV_GSTR 584
#define KV_WSTR (4 * KV_GSTR)                     // 2336
#define KV_RSTR 36
#define SMEM_FLOATS (SMF_KV + NWARP * KV_WSTR)    // 17792 floats = 71168 B

extern "C" __global__ void __launch_bounds__(CTA, 2)
tfenc_kernel(const float* __restrict__ x,
             const float* __restrict__ Wq, const float* __restrict__ bq,
             const float* __restrict__ Wk, const float* __restrict__ bk,
             const float* __restrict__ Wv, const float* __restrict__ bv,
             const float* __restrict__ Wo, const float* __restrict__ bo,
             const float* __restrict__ W1, const float* __restrict__ b1,
             const float* __restrict__ W2, const float* __restrict__ b2,
             float* __restrict__ out)
{
    extern __shared__ float sm[];
    float* sWq = sm;
    float* sWk = sm + 1024;
    float* sWv = sm + 2048;
    float* sWo = sm + 3072;
    float* sW1 = sm + 4096;
    float* sW2 = sm + 6144;
    float* sB  = sm + SMF_B;
    float* sKV = sm + SMF_KV;

    const int tid = threadIdx.x;
    for (int i = tid; i < 1024; i += CTA) {
        sWq[i] = Wq[i]; sWk[i] = Wk[i]; sWv[i] = Wv[i]; sWo[i] = Wo[i];
    }
    for (int i = tid; i < 2048; i += CTA) { sW1[i] = W1[i]; sW2[i] = W2[i]; }
    if (tid < 32) {
        sB[tid] = bq[tid]; sB[32 + tid] = bk[tid]; sB[64 + tid] = bv[tid];
        sB[96 + tid] = bo[tid]; sB[192 + tid] = b2[tid];
    }
    if (tid >= 32 && tid < 96) sB[96 + tid] = b1[tid - 32];   // -> sB[128..191]
    __syncthreads();

    const int warp = tid >> 5, lane = tid & 31;
    const int g = lane >> 4;      // which half of the warp
    const int t = lane & 15;      // token owned by this lane
    float* kvA = sKV + warp * KV_WSTR + g * KV_GSTR;          // batch quad*4 + g
    float* kvB = sKV + warp * KV_WSTR + (2 + g) * KV_GSTR;    // batch quad*4 + 2 + g

    const int nquads = NBAT / 4;
    const int qstride = gridDim.x * NWARP;
    for (int qd = blockIdx.x * NWARP + warp; qd < nquads; qd += qstride) {
        const int bA = qd * 4 + g;
        const int bB = bA + 2;
        const float* xrowA = x + ((long)bA * SEQ + t) * DDIM;
        const float* xrowB = x + ((long)bB * SEQ + t) * DDIM;

        float xvA[32], xvB[32];
#pragma unroll
        for (int j = 0; j < 8; j++) {
            float4 fA = reinterpret_cast<const float4*>(xrowA)[j];
            float4 fB = reinterpret_cast<const float4*>(xrowB)[j];
            xvA[4*j] = fA.x; xvA[4*j+1] = fA.y; xvA[4*j+2] = fA.z; xvA[4*j+3] = fA.w;
            xvB[4*j] = fB.x; xvB[4*j+1] = fB.y; xvB[4*j+2] = fB.z; xvB[4*j+3] = fB.w;
        }

        // ---- K -> shared (first, so Q gemm hides the stores) ----
        {
            u64 aA[16], aB[16];
#pragma unroll
            for (int p = 0; p < 16; p++) { aA[p] = 0ULL; aB[p] = 0ULL; }
            gemm_32to32_dual(sWk, xvA, xvB, aA, aB);
            bias16(aA, sB + 32); bias16(aB, sB + 32);
            store_row(kvA + t * KV_RSTR, aA);
            store_row(kvB + t * KV_RSTR, aB);
        }

        // ---- Q (kept packed as pairs for the scores stage) ----
        u64 q2A[16], q2B[16];
#pragma unroll
        for (int p = 0; p < 16; p++) { q2A[p] = 0ULL; q2B[p] = 0ULL; }
        gemm_32to32_dual(sWq, xvA, xvB, q2A, q2B);
        bias16(q2A, sB + 0); bias16(q2B, sB + 0);
        __syncwarp();

        // ---- scores ----
        float scA[16], scB[16];
#pragma unroll
        for (int tt = 0; tt < 16; tt++) {
            const ulonglong2* krA = reinterpret_cast<const ulonglong2*>(kvA + tt * KV_RSTR);
            const ulonglong2* krB = reinterpret_cast<const ulonglong2*>(kvB + tt * KV_RSTR);
            u64 aA0 = 0ULL, aA1 = 0ULL, aB0 = 0ULL, aB1 = 0ULL;
#pragma unroll
            for (int j = 0; j < 8; j++) {
                ulonglong2 kkA = krA[j];
                ulonglong2 kkB = krB[j];
                fma2(aA0, q2A[2*j],   kkA.x);
                fma2(aA1, q2A[2*j+1], kkA.y);
                fma2(aB0, q2B[2*j],   kkB.x);
                fma2(aB1, q2B[2*j+1], kkB.y);
            }
            float l0, h0, l1, h1;
            upk2(aA0, l0, h0); upk2(aA1, l1, h1);
            scA[tt] = (l0 + h0 + l1 + h1) * 0.17677669529663689f;
            upk2(aB0, l0, h0); upk2(aB1, l1, h1);
            scB[tt] = (l0 + h0 + l1 + h1) * 0.17677669529663689f;
        }
        __syncwarp();   // all lanes done reading K before V overwrites buffer

        // ---- V -> shared (reuse buffer) ----
        {
            u64 aA[16], aB[16];
#pragma unroll
            for (int p = 0; p < 16; p++) { aA[p] = 0ULL; aB[p] = 0ULL; }
            gemm_32to32_dual(sWv, xvA, xvB, aA, aB);
            bias16(aA, sB + 64); bias16(aB, sB + 64);
            store_row(kvA + t * KV_RSTR, aA);
            store_row(kvB + t * KV_RSTR, aB);
        }

        // ---- softmax (hides V stores) ----
        {
            float m = scA[0];
#pragma unroll
            for (int i = 1; i < 16; i++) m = fmaxf(m, scA[i]);
            float s = 0.f;
#pragma unroll
            for (int i = 0; i < 16; i++) { float e = __expf(scA[i] - m); scA[i] = e; s += e; }
            float inv = 1.0f / s;
#pragma unroll
            for (int i = 0; i < 16; i++) scA[i] *= inv;
            m = scB[0];
#pragma unroll
            for (int i = 1; i < 16; i++) m = fmaxf(m, scB[i]);
            s = 0.f;
#pragma unroll
            for (int i = 0; i < 16; i++) { float e = __expf(scB[i] - m); scB[i] = e; s += e; }
            inv = 1.0f / s;
#pragma unroll
            for (int i = 0; i < 16; i++) scB[i] *= inv;
        }
        __syncwarp();

        // ---- context = sum_t attn_t * v_t ----
        u64 c2A[16], c2B[16];
#pragma unroll
        for (int p = 0; p < 16; p++) { c2A[p] = 0ULL; c2B[p] = 0ULL; }
#pragma unroll
        for (int tt = 0; tt < 16; tt++) {
            const u64 adA = pk2(scA[tt], scA[tt]);
            const u64 adB = pk2(scB[tt], scB[tt]);
            const ulonglong2* vrA = reinterpret_cast<const ulonglong2*>(kvA + tt * KV_RSTR);
            const ulonglong2* vrB = reinterpret_cast<const ulonglong2*>(kvB + tt * KV_RSTR);
#pragma unroll
            for (int j = 0; j < 8; j++) {
                ulonglong2 vvA = vrA[j];
                ulonglong2 vvB = vrB[j];
                fma2(c2A[2*j],   adA, vvA.x);
                fma2(c2A[2*j+1], adA, vvA.y);
                fma2(c2B[2*j],   adB, vvB.x);
                fma2(c2B[2*j+1], adB, vvB.y);
            }
        }
        __syncwarp();   // done reading V before next iteration's K store

        // ---- Wo + residual 1 (y overwrites xv) ----
        {
            float cA[32], cB[32];
#pragma unroll
            for (int p = 0; p < 16; p++) {
                upk2(c2A[p], cA[2*p], cA[2*p+1]);
                upk2(c2B[p], cB[2*p], cB[2*p+1]);
            }
            u64 yA[16], yB[16];
#pragma unroll
            for (int p = 0; p < 16; p++) { yA[p] = 0ULL; yB[p] = 0ULL; }
            gemm_32to32_dual(sWo, cA, cB, yA, yB);
#pragma unroll
            for (int p = 0; p < 16; p++) {
                float lo, hi;
                upk2(yA[p], lo, hi);
                xvA[2*p]   = xvA[2*p]   + lo + sB[96 + 2*p];
                xvA[2*p+1] = xvA[2*p+1] + hi + sB[96 + 2*p+1];
                upk2(yB[p], lo, hi);
                xvB[2*p]   = xvB[2*p]   + lo + sB[96 + 2*p];
                xvB[2*p+1] = xvB[2*p+1] + hi + sB[96 + 2*p+1];
            }
        }
        // xvA/xvB now hold y (post-residual-1)

        // ---- FFN in two 32-wide halves, FFN2 fused per half ----
        u64 z2A[16], z2B[16];
#pragma unroll
        for (int p = 0; p < 16; p++) { z2A[p] = 0ULL; z2B[p] = 0ULL; }
#pragma unroll
        for (int half = 0; half < 2; half++) {
            u64 hA[16], hB[16];
#pragma unroll
            for (int p = 0; p < 16; p++) { hA[p] = 0ULL; hB[p] = 0ULL; }
#pragma unroll
            for (int k = 0; k < 32; k++) {
                u64 yda = pk2(xvA[k], xvA[k]);
                u64 ydb = pk2(xvB[k], xvB[k]);
                const ulonglong2* w =
                    reinterpret_cast<const ulonglong2*>(sW1 + k * 64 + half * 32);
#pragma unroll
                for (int j = 0; j < 8; j++) {
                    ulonglong2 ww = w[j];
                    fma2(hA[2*j],   yda, ww.x);
                    fma2(hA[2*j+1], yda, ww.y);
                    fma2(hB[2*j],   ydb, ww.x);
                    fma2(hB[2*j+1], ydb, ww.y);
                }
            }
            // bias + relu + FFN2 accumulate for this half's 32 features
#pragma unroll
            for (int p = 0; p < 16; p++) {
                float a0, a1, b0, b1v;
                upk2(hA[p], a0, a1);
                upk2(hB[p], b0, b1v);
                const float bi0 = sB[128 + half * 32 + 2*p];
                const float bi1 = sB[128 + half * 32 + 2*p + 1];
                a0 = fmaxf(a0 + bi0, 0.f); a1 = fmaxf(a1 + bi1, 0.f);
                b0 = fmaxf(b0 + bi0, 0.f); b1v = fmaxf(b1v + bi1, 0.f);
                // feature f0 = half*32 + 2p, f1 = f0+1
                {
                    const u64 hdA = pk2(a0, a0), hdB = pk2(b0, b0);
                    const ulonglong2* w = reinterpret_cast<const ulonglong2*>(
                        sW2 + (half * 32 + 2*p) * 32);
#pragma unroll
                    for (int j = 0; j < 8; j++) {
                        ulonglong2 ww = w[j];
                        fma2(z2A[2*j],   hdA, ww.x);
                        fma2(z2A[2*j+1], hdA, ww.y);
                        fma2(z2B[2*j],   hdB, ww.x);
                        fma2(z2B[2*j+1], hdB, ww.y);
                    }
                }
                {
                    const u64 hdA = pk2(a1, a1), hdB = pk2(b1v, b1v);
                    const ulonglong2* w = reinterpret_cast<const ulonglong2*>(
                        sW2 + (half * 32 + 2*p + 1) * 32);
#pragma unroll
                    for (int j = 0; j < 8; j++) {
                        ulonglong2 ww = w[j];
                        fma2(z2A[2*j],   hdA, ww.x);
                        fma2(z2A[2*j+1], hdA, ww.y);
                        fma2(z2B[2*j],   hdB, ww.x);
                        fma2(z2B[2*j+1], hdB, ww.y);
                    }
                }
            }
        }

        // ---- residual 2 + store ----
        float* orowA = out + ((long)bA * SEQ + t) * DDIM;
        float* orowB = out + ((long)bB * SEQ + t) * DDIM;
#pragma unroll
        for (int j = 0; j < 8; j++) {
            float l0, h0v, l1, h1v;
            float4 f;
            upk2(z2A[2*j], l0, h0v); upk2(z2A[2*j+1], l1, h1v);
            f.x = xvA[4*j]   + l0  + sB[192 + 4*j];
            f.y = xvA[4*j+1] + h0v + sB[192 + 4*j+1];
            f.z = xvA[4*j+2] + l1  + sB[192 + 4*j+2];
            f.w = xvA[4*j+3] + h1v + sB[192 + 4*j+3];
            reinterpret_cast<float4*>(orowA)[j] = f;
            upk2(z2B[2*j], l0, h0v); upk2(z2B[2*j+1], l1, h1v);
            f.x = xvB[4*j]   + l0  + sB[192 + 4*j];
            f.y = xvB[4*j+1] + h0v + sB[192 + 4*j+1];
            f.z = xvB[4*j+2] + l1  + sB[192 + 4*j+2];
            f.w = xvB[4*j+3] + h1v + sB[192 + 4*j+3];
            reinterpret_cast<float4*>(orowB)[j] = f;
        }
    }
}

extern "C" void kernel_launch(void* const* d_in, const int* in_sizes, int n_in,
                              void* d_out, int out_size) {
    (void)in_sizes; (void)n_in; (void)out_size;
    const float* x  = (const float*)d_in[0];
    const float* Wq = (const float*)d_in[1];
    const float* bq = (const float*)d_in[2];
    const float* Wk = (const float*)d_in[3];
    const float* bk = (const float*)d_in[4];
    const float* Wv = (const float*)d_in[5];
    const float* bv = (const float*)d_in[6];
    const float* Wo = (const float*)d_in[7];
    const float* bo = (const float*)d_in[8];
    const float* W1 = (const float*)d_in[9];
    const float* b1 = (const float*)d_in[10];
    const float* W2 = (const float*)d_in[11];
    const float* b2 = (const float*)d_in[12];
    float* out = (float*)d_out;

    const int smem_bytes = SMEM_FLOATS * 4;   // 71168
    cudaFuncSetAttribute(tfenc_kernel, cudaFuncAttributeMaxDynamicSharedMemorySize, smem_bytes);
    tfenc_kernel<<<NBLK, CTA, smem_bytes>>>(x, Wq, bq, Wk, bk, Wv, bv, Wo, bo,
                                            W1, b1, W2, b2, out);
}

// round 3
// speedup vs baseline: 1.2507x; 1.0693x over previous
#include <cuda_runtime.h>

// TinyFormerEncoder: B=65536, S=16, D=32, FFN=64, fp32.
// Round 3: dual-token per lane (weight LDS amortized over 2 tokens) with
// register-pressure fixes to reach 3 CTAs/SM (12 warps):
//  - y (post-residual-1) manually spilled to the per-warp smem KV buffer
//    (dead after context); each lane touches only its own row -> no syncs.
//  - x re-loaded from global at residual-1 instead of living in regs.

#define DDIM 32
#define SEQ  16
#define FFND 64
#define NBAT 65536
#define NWARP 4
#define CTA   128
#define NBLK  444   // 148 SMs * 3 CTAs

typedef unsigned long long u64;

__device__ __forceinline__ u64 pk2(float lo, float hi) {
    u64 r; asm("mov.b64 %0,{%1,%2};" : "=l"(r) : "f"(lo), "f"(hi)); return r;
}
__device__ __forceinline__ void upk2(u64 p, float &lo, float &hi) {
    asm("mov.b64 {%0,%1},%2;" : "=f"(lo), "=f"(hi) : "l"(p));
}
__device__ __forceinline__ void fma2(u64 &d, u64 a, u64 b) {
    asm("fma.rn.f32x2 %0,%1,%2,%0;" : "+l"(d) : "l"(a), "l"(b));
}
__device__ __forceinline__ u64 add2(u64 a, u64 b) {
    u64 r; asm("add.rn.f32x2 %0,%1,%2;" : "=l"(r) : "l"(a), "l"(b)); return r;
}

// Dual-token 32->32 GEMM from shared W[32][32]. One weight row load feeds both.
__device__ __forceinline__ void gemm_32to32_dual(const float* __restrict__ Wsh,
                                                 const float* xa, const float* xb,
                                                 u64* accA, u64* accB) {
#pragma unroll
    for (int k = 0; k < 32; k++) {
        u64 xda = pk2(xa[k], xa[k]);
        u64 xdb = pk2(xb[k], xb[k]);
        const ulonglong2* w = reinterpret_cast<const ulonglong2*>(Wsh + k * 32);
#pragma unroll
        for (int j = 0; j < 8; j++) {
            ulonglong2 ww = w[j];
            fma2(accA[2 * j],     xda, ww.x);
            fma2(accA[2 * j + 1], xda, ww.y);
            fma2(accB[2 * j],     xdb, ww.x);
            fma2(accB[2 * j + 1], xdb, ww.y);
        }
    }
}

__device__ __forceinline__ void bias16(u64* acc, const float* __restrict__ bsh) {
    const ulonglong2* bb = reinterpret_cast<const ulonglong2*>(bsh);
#pragma unroll
    for (int j = 0; j < 8; j++) {
        ulonglong2 b = bb[j];
        acc[2 * j]     = add2(acc[2 * j],     b.x);
        acc[2 * j + 1] = add2(acc[2 * j + 1], b.y);
    }
}

__device__ __forceinline__ void store_row(float* row, const u64* acc) {
    ulonglong2* rp = reinterpret_cast<ulonglong2*>(row);
#pragma unroll
    for (int j = 0; j < 8; j++) {
        ulonglong2 tt; tt.x = acc[2 * j]; tt.y = acc[2 * j + 1];
        rp[j] = tt;
    }
}

// Shared layout (floats): Wq 0, Wk 1024, Wv 2048, Wo 3072, W1 4096(2048), W2 6144(2048),
// biases 8192..8415, pad to 8448, then per-warp KV buffers:
// 4 groups/warp, group stride 584, row stride 36.
#define SMF_B   8192
#define SMF_KV  8448
#define KV_GSTR 584
#define KV_WSTR (4 * KV_GSTR)                     // 2336
#define KV_RSTR 36
#define SMEM_FLOATS (SMF_KV + NWARP * KV_WSTR)    // 17792 floats = 71168 B

extern "C" __global__ void __launch_bounds__(CTA, 3)
tfenc_kernel(const float* __restrict__ x,
             const float* __restrict__ Wq, const float* __restrict__ bq,
             const float* __restrict__ Wk, const float* __restrict__ bk,
             const float* __restrict__ Wv, const float* __restrict__ bv,
             const float* __restrict__ Wo, const float* __restrict__ bo,
             const float* __restrict__ W1, const float* __restrict__ b1,
             const float* __restrict__ W2, const float* __restrict__ b2,
             float* __restrict__ out)
{
    extern __shared__ float sm[];
    float* sWq = sm;
    float* sWk = sm + 1024;
    float* sWv = sm + 2048;
    float* sWo = sm + 3072;
    float* sW1 = sm + 4096;
    float* sW2 = sm + 6144;
    float* sB  = sm + SMF_B;
    float* sKV = sm + SMF_KV;

    const int tid = threadIdx.x;
    for (int i = tid; i < 1024; i += CTA) {
        sWq[i] = Wq[i]; sWk[i] = Wk[i]; sWv[i] = Wv[i]; sWo[i] = Wo[i];
    }
    for (int i = tid; i < 2048; i += CTA) { sW1[i] = W1[i]; sW2[i] = W2[i]; }
    if (tid < 32) {
        sB[tid] = bq[tid]; sB[32 + tid] = bk[tid]; sB[64 + tid] = bv[tid];
        sB[96 + tid] = bo[tid]; sB[192 + tid] = b2[tid];
    }
    if (tid >= 32 && tid < 96) sB[96 + tid] = b1[tid - 32];   // -> sB[128..191]
    __syncthreads();

    const int warp = tid >> 5, lane = tid & 31;
    const int g = lane >> 4;      // which half of the warp
    const int t = lane & 15;      // token owned by this lane
    float* kvA = sKV + warp * KV_WSTR + g * KV_GSTR;          // batch quad*4 + g
    float* kvB = sKV + warp * KV_WSTR + (2 + g) * KV_GSTR;    // batch quad*4 + 2 + g
    float* rowA = kvA + t * KV_RSTR;   // this lane's own row (K/V/y stage)
    float* rowB = kvB + t * KV_RSTR;

    const int nquads = NBAT / 4;
    const int qstride = gridDim.x * NWARP;
    for (int qd = blockIdx.x * NWARP + warp; qd < nquads; qd += qstride) {
        const int bA = qd * 4 + g;
        const int bB = bA + 2;
        const float* xrowA = x + ((long)bA * SEQ + t) * DDIM;
        const float* xrowB = x + ((long)bB * SEQ + t) * DDIM;

        float xvA[32], xvB[32];
#pragma unroll
        for (int j = 0; j < 8; j++) {
            float4 fA = reinterpret_cast<const float4*>(xrowA)[j];
            float4 fB = reinterpret_cast<const float4*>(xrowB)[j];
            xvA[4*j] = fA.x; xvA[4*j+1] = fA.y; xvA[4*j+2] = fA.z; xvA[4*j+3] = fA.w;
            xvB[4*j] = fB.x; xvB[4*j+1] = fB.y; xvB[4*j+2] = fB.z; xvB[4*j+3] = fB.w;
        }

        // ---- K -> shared ----
        {
            u64 aA[16], aB[16];
#pragma unroll
            for (int p = 0; p < 16; p++) { aA[p] = 0ULL; aB[p] = 0ULL; }
            gemm_32to32_dual(sWk, xvA, xvB, aA, aB);
            bias16(aA, sB + 32); bias16(aB, sB + 32);
            store_row(rowA, aA);
            store_row(rowB, aB);
        }

        // ---- Q ----
        u64 q2A[16], q2B[16];
#pragma unroll
        for (int p = 0; p < 16; p++) { q2A[p] = 0ULL; q2B[p] = 0ULL; }
        gemm_32to32_dual(sWq, xvA, xvB, q2A, q2B);
        bias16(q2A, sB + 0); bias16(q2B, sB + 0);
        __syncwarp();

        // ---- scores ----
        float scA[16], scB[16];
#pragma unroll
        for (int tt = 0; tt < 16; tt++) {
            const ulonglong2* krA = reinterpret_cast<const ulonglong2*>(kvA + tt * KV_RSTR);
            const ulonglong2* krB = reinterpret_cast<const ulonglong2*>(kvB + tt * KV_RSTR);
            u64 aA0 = 0ULL, aA1 = 0ULL, aB0 = 0ULL, aB1 = 0ULL;
#pragma unroll
            for (int j = 0; j < 8; j++) {
                ulonglong2 kkA = krA[j];
                ulonglong2 kkB = krB[j];
                fma2(aA0, q2A[2*j],   kkA.x);
                fma2(aA1, q2A[2*j+1], kkA.y);
                fma2(aB0, q2B[2*j],   kkB.x);
                fma2(aB1, q2B[2*j+1], kkB.y);
            }
            float l0, h0, l1, h1;
            upk2(aA0, l0, h0); upk2(aA1, l1, h1);
            scA[tt] = (l0 + h0 + l1 + h1) * 0.17677669529663689f;
            upk2(aB0, l0, h0); upk2(aB1, l1, h1);
            scB[tt] = (l0 + h0 + l1 + h1) * 0.17677669529663689f;
        }
        __syncwarp();   // all lanes done reading K before V overwrites buffer

        // ---- V -> shared (reuse buffer; last use of xv) ----
        {
            u64 aA[16], aB[16];
#pragma unroll
            for (int p = 0; p < 16; p++) { aA[p] = 0ULL; aB[p] = 0ULL; }
            gemm_32to32_dual(sWv, xvA, xvB, aA, aB);
            bias16(aA, sB + 64); bias16(aB, sB + 64);
            store_row(rowA, aA);
            store_row(rowB, aB);
        }

        // ---- softmax (hides V stores) ----
        {
            float m = scA[0];
#pragma unroll
            for (int i = 1; i < 16; i++) m = fmaxf(m, scA[i]);
            float s = 0.f;
#pragma unroll
            for (int i = 0; i < 16; i++) { float e = __expf(scA[i] - m); scA[i] = e; s += e; }
            float inv = 1.0f / s;
#pragma unroll
            for (int i = 0; i < 16; i++) scA[i] *= inv;
            m = scB[0];
#pragma unroll
            for (int i = 1; i < 16; i++) m = fmaxf(m, scB[i]);
            s = 0.f;
#pragma unroll
            for (int i = 0; i < 16; i++) { float e = __expf(scB[i] - m); scB[i] = e; s += e; }
            inv = 1.0f / s;
#pragma unroll
            for (int i = 0; i < 16; i++) scB[i] *= inv;
        }
        __syncwarp();

        // ---- context = sum_t attn_t * v_t ----
        u64 c2A[16], c2B[16];
#pragma unroll
        for (int p = 0; p < 16; p++) { c2A[p] = 0ULL; c2B[p] = 0ULL; }
#pragma unroll
        for (int tt = 0; tt < 16; tt++) {
            const u64 adA = pk2(scA[tt], scA[tt]);
            const u64 adB = pk2(scB[tt], scB[tt]);
            const ulonglong2* vrA = reinterpret_cast<const ulonglong2*>(kvA + tt * KV_RSTR);
            const ulonglong2* vrB = reinterpret_cast<const ulonglong2*>(kvB + tt * KV_RSTR);
#pragma unroll
            for (int j = 0; j < 8; j++) {
                ulonglong2 vvA = vrA[j];
                ulonglong2 vvB = vrB[j];
                fma2(c2A[2*j],   adA, vvA.x);
                fma2(c2A[2*j+1], adA, vvA.y);
                fma2(c2B[2*j],   adB, vvB.x);
                fma2(c2B[2*j+1], adB, vvB.y);
            }
        }
        __syncwarp();   // all lanes done reading V before y overwrites buffer

        // ---- Wo + residual 1 (x re-loaded from global); y -> smem rows ----
        {
            float cA[32], cB[32];
#pragma unroll
            for (int p = 0; p < 16; p++) {
                upk2(c2A[p], cA[2*p], cA[2*p+1]);
                upk2(c2B[p], cB[2*p], cB[2*p+1]);
            }
            u64 yA[16], yB[16];
#pragma unroll
            for (int p = 0; p < 16; p++) { yA[p] = 0ULL; yB[p] = 0ULL; }
            gemm_32to32_dual(sWo, cA, cB, yA, yB);
            // y = x + (c@Wo) + bo ; write to own smem row (manual spill)
#pragma unroll
            for (int j = 0; j < 8; j++) {
                float4 fA = reinterpret_cast<const float4*>(xrowA)[j];
                float4 fB = reinterpret_cast<const float4*>(xrowB)[j];
                float l0, h0v, l1, h1v;
                float4 o;
                upk2(yA[2*j], l0, h0v); upk2(yA[2*j+1], l1, h1v);
                o.x = fA.x + l0  + sB[96 + 4*j];
                o.y = fA.y + h0v + sB[96 + 4*j+1];
                o.z = fA.z + l1  + sB[96 + 4*j+2];
                o.w = fA.w + h1v + sB[96 + 4*j+3];
                reinterpret_cast<float4*>(rowA)[j] = o;
                upk2(yB[2*j], l0, h0v); upk2(yB[2*j+1], l1, h1v);
                o.x = fB.x + l0  + sB[96 + 4*j];
                o.y = fB.y + h0v + sB[96 + 4*j+1];
                o.z = fB.z + l1  + sB[96 + 4*j+2];
                o.w = fB.w + h1v + sB[96 + 4*j+3];
                reinterpret_cast<float4*>(rowB)[j] = o;
            }
        }
        // rowA/rowB now hold y for this lane's tokens. No cross-lane access.

        // ---- FFN in two 32-wide halves, FFN2 fused per half; y read from smem ----
        u64 z2A[16], z2B[16];
#pragma unroll
        for (int p = 0; p < 16; p++) { z2A[p] = 0ULL; z2B[p] = 0ULL; }
        const float2* yAp = reinterpret_cast<const float2*>(rowA);
        const float2* yBp = reinterpret_cast<const float2*>(rowB);
#pragma unroll
        for (int half = 0; half < 2; half++) {
            u64 hA[16], hB[16];
#pragma unroll
            for (int p = 0; p < 16; p++) { hA[p] = 0ULL; hB[p] = 0ULL; }
#pragma unroll
            for (int kp = 0; kp < 16; kp++) {
                float2 ya = yAp[kp];
                float2 yb = yBp[kp];
                u64 a0 = pk2(ya.x, ya.x), a1 = pk2(ya.y, ya.y);
                u64 b0 = pk2(yb.x, yb.x), b1v = pk2(yb.y, yb.y);
                const ulonglong2* w0 =
                    reinterpret_cast<const ulonglong2*>(sW1 + (2*kp)   * 64 + half * 32);
                const ulonglong2* w1 =
                    reinterpret_cast<const ulonglong2*>(sW1 + (2*kp+1) * 64 + half * 32);
#pragma unroll
                for (int j = 0; j < 8; j++) {
                    ulonglong2 ww0 = w0[j];
                    ulonglong2 ww1 = w1[j];
                    fma2(hA[2*j],   a0, ww0.x);
                    fma2(hA[2*j+1], a0, ww0.y);
                    fma2(hB[2*j],   b0, ww0.x);
                    fma2(hB[2*j+1], b0, ww0.y);
                    fma2(hA[2*j],   a1, ww1.x);
                    fma2(hA[2*j+1], a1, ww1.y);
                    fma2(hB[2*j],   b1v, ww1.x);
                    fma2(hB[2*j+1], b1v, ww1.y);
                }
            }
            // bias + relu + FFN2 accumulate for this half's 32 features
#pragma unroll
            for (int p = 0; p < 16; p++) {
                float a0, a1, b0, b1v;
                upk2(hA[p], a0, a1);
                upk2(hB[p], b0, b1v);
                const float bi0 = sB[128 + half * 32 + 2*p];
                const float bi1 = sB[128 + half * 32 + 2*p + 1];
                a0 = fmaxf(a0 + bi0, 0.f); a1 = fmaxf(a1 + bi1, 0.f);
                b0 = fmaxf(b0 + bi0, 0.f); b1v = fmaxf(b1v + bi1, 0.f);
                {
                    const u64 hdA = pk2(a0, a0), hdB = pk2(b0, b0);
                    const ulonglong2* w = reinterpret_cast<const ulonglong2*>(
                        sW2 + (half * 32 + 2*p) * 32);
#pragma unroll
                    for (int j = 0; j < 8; j++) {
                        ulonglong2 ww = w[j];
                        fma2(z2A[2*j],   hdA, ww.x);
                        fma2(z2A[2*j+1], hdA, ww.y);
                        fma2(z2B[2*j],   hdB, ww.x);
                        fma2(z2B[2*j+1], hdB, ww.y);
                    }
                }
                {
                    const u64 hdA = pk2(a1, a1), hdB = pk2(b1v, b1v);
                    const ulonglong2* w = reinterpret_cast<const ulonglong2*>(
                        sW2 + (half * 32 + 2*p + 1) * 32);
#pragma unroll
                    for (int j = 0; j < 8; j++) {
                        ulonglong2 ww = w[j];
                        fma2(z2A[2*j],   hdA, ww.x);
                        fma2(z2A[2*j+1], hdA, ww.y);
                        fma2(z2B[2*j],   hdB, ww.x);
                        fma2(z2B[2*j+1], hdB, ww.y);
                    }
                }
            }
        }

        // ---- residual 2 (y from own smem row) + store ----
        float* orowA = out + ((long)bA * SEQ + t) * DDIM;
        float* orowB = out + ((long)bB * SEQ + t) * DDIM;
#pragma unroll
        for (int j = 0; j < 8; j++) {
            float4 yA4 = reinterpret_cast<const float4*>(rowA)[j];
            float4 yB4 = reinterpret_cast<const float4*>(rowB)[j];
            float l0, h0v, l1, h1v;
            float4 f;
            upk2(z2A[2*j], l0, h0v); upk2(z2A[2*j+1], l1, h1v);
            f.x = yA4.x + l0  + sB[192 + 4*j];
            f.y = yA4.y + h0v + sB[192 + 4*j+1];
            f.z = yA4.z + l1  + sB[192 + 4*j+2];
            f.w = yA4.w + h1v + sB[192 + 4*j+3];
            reinterpret_cast<float4*>(orowA)[j] = f;
            upk2(z2B[2*j], l0, h0v); upk2(z2B[2*j+1], l1, h1v);
            f.x = yB4.x + l0  + sB[192 + 4*j];
            f.y = yB4.y + h0v + sB[192 + 4*j+1];
            f.z = yB4.z + l1  + sB[192 + 4*j+2];
            f.w = yB4.w + h1v + sB[192 + 4*j+3];
            reinterpret_cast<float4*>(orowB)[j] = f;
        }
        // Next iteration's K store only overwrites this lane's own rows,
        // which only this lane read above -> no syncwarp needed here.
    }
}

extern "C" void kernel_launch(void* const* d_in, const int* in_sizes, int n_in,
                              void* d_out, int out_size) {
    (void)in_sizes; (void)n_in; (void)out_size;
    const float* x  = (const float*)d_in[0];
    const float* Wq = (const float*)d_in[1];
    const float* bq = (const float*)d_in[2];
    const float* Wk = (const float*)d_in[3];
    const float* bk = (const float*)d_in[4];
    const float* Wv = (const float*)d_in[5];
    const float* bv = (const float*)d_in[6];
    const float* Wo = (const float*)d_in[7];
    const float* bo = (const float*)d_in[8];
    const float* W1 = (const float*)d_in[9];
    const float* b1 = (const float*)d_in[10];
    const float* W2 = (const float*)d_in[11];
    const float* b2 = (const float*)d_in[12];
    float* out = (float*)d_out;

    const int smem_bytes = SMEM_FLOATS * 4;   // 71168
    cudaFuncSetAttribute(tfenc_kernel, cudaFuncAttributeMaxDynamicSharedMemorySize, smem_bytes);
    tfenc_kernel<<<NBLK, CTA, smem_bytes>>>(x, Wq, bq, Wk, bk, Wv, bv, Wo, bo,
                                            W1, b1, W2, b2, out);
}